// round 9
// baseline (speedup 1.0000x reference)
#include <cuda_runtime.h>
#include <cstdint>

// RealNVP: 15 coupling layers, two MLPs 1->32->16->1 per layer (leaky_relu 0.01),
// log_scale = tanh(mlp_s(x1))@sw + sb ; z2' = exp(log_scale)*x2 + mlp_t(x1)
// Output: [ concat(z1,z2) (N,2) row-major | ld (N,1) ] -> 3N floats.
//
// R9 = R8 body (R5 + branch-free MUFU tanh; 2870us, fma=72.6%, regs=130)
// with TPB 384 -> 480. Occupancy was the limiter: 12 warps/SM = 3/SMSP,
// issue=59%. Reg ceiling 65536/130/32 = 15.7 warps -> 15 warps fits without
// forcing ptxas below its natural 130 allocation (cap@480 = 136).

#define NLAYERS 15
#define LAYER_STRIDE 678                // packed 8B units per layer
#define SMEM_UNITS (NLAYERS * LAYER_STRIDE)
#define SMEM_BYTES (SMEM_UNITS * 8)     // 81,360 B
#define TPB 480

__device__ __forceinline__ uint64_t pk2(float a, float b) {
    uint64_t r; asm("mov.b64 %0, {%1, %2};" : "=l"(r) : "f"(a), "f"(b)); return r;
}
__device__ __forceinline__ uint64_t dup2(float a) {
    uint64_t r; asm("mov.b64 %0, {%1, %1};" : "=l"(r) : "f"(a)); return r;
}
__device__ __forceinline__ void up2(uint64_t v, float& a, float& b) {
    asm("mov.b64 {%0, %1}, %2;" : "=f"(a), "=f"(b) : "l"(v));
}
__device__ __forceinline__ uint64_t fma2(uint64_t a, uint64_t b, uint64_t c) {
    uint64_t d; asm("fma.rn.f32x2 %0, %1, %2, %3;" : "=l"(d) : "l"(a), "l"(b), "l"(c)); return d;
}
__device__ __forceinline__ uint64_t mul2(uint64_t a, uint64_t b) {
    uint64_t d; asm("mul.rn.f32x2 %0, %1, %2;" : "=l"(d) : "l"(a), "l"(b)); return d;
}
__device__ __forceinline__ uint64_t add2(uint64_t a, uint64_t b) {
    uint64_t d; asm("add.rn.f32x2 %0, %1, %2;" : "=l"(d) : "l"(a), "l"(b)); return d;
}

// leaky_relu(h, 0.01) == 0.505*h + 0.495*|h|   (branch-free, packed; LOP3 abs)
__device__ __forceinline__ uint64_t lrelu2(uint64_t h) {
    uint64_t a = h & 0x7FFFFFFF7FFFFFFFULL;
    uint64_t m = mul2(h, pk2(0.505f, 0.505f));
    return fma2(a, pk2(0.495f, 0.495f), m);
}

// Branch-free tanh: 1 - 2/(exp(2x)+1). Robust: e->inf => 1, e->0 => -1.
__device__ __forceinline__ float fast_tanh(float x) {
    float e = __expf(2.0f * x);
    float r = __frcp_rn(e + 1.0f);
    return fmaf(-2.0f, r, 1.0f);
}

// Per-layer per-MLP SMEM layout (8B units; every sub-array 16B-aligned):
//   [0,64)    interleaved DUPLICATED (W1[i],W1[i]),(b1[i],b1[i])   (32 x 16B)
//   [64,320)  W2 rows, PLAIN pairs: row i = 16 floats = 8 units    (32 x 4 x 16B)
//   [320,328) b2 plain pairs
//   [328,336) W3 plain pairs
//   [336]     (b3, 0.0f), [337] pad
// MLP t at +338; sw dup at [676], sb dup at [677]. LAYER_STRIDE=678.

// Quad MLP: 4 points (xa = pts 0,1 ; xb = pts 2,3) share every weight load.
// h2 accumulators are packed over hidden-unit pairs (j, j+1) per point.
__device__ __forceinline__ void mlp2_quad(
    uint64_t xa, uint64_t xb, const unsigned long long* __restrict__ p,
    uint64_t& oa, uint64_t& ob)
{
    uint64_t h0[8], h1r[8], h2r[8], h3r[8];
    const ulonglong2* b2v = reinterpret_cast<const ulonglong2*>(p + 320);
#pragma unroll
    for (int jj = 0; jj < 4; jj++) {
        ulonglong2 b = b2v[jj];
        h0[2*jj] = b.x;  h0[2*jj+1] = b.y;
        h1r[2*jj] = b.x; h1r[2*jj+1] = b.y;
        h2r[2*jj] = b.x; h2r[2*jj+1] = b.y;
        h3r[2*jj] = b.x; h3r[2*jj+1] = b.y;
    }
    const ulonglong2* w1b1 = reinterpret_cast<const ulonglong2*>(p);
    const ulonglong2* W2   = reinterpret_cast<const ulonglong2*>(p + 64);
#pragma unroll 4
    for (int i = 0; i < 32; i++) {
        ulonglong2 wb = w1b1[i];
        uint64_t ha = lrelu2(fma2(xa, wb.x, wb.y));   // (h1_p0, h1_p1)
        uint64_t hb = lrelu2(fma2(xb, wb.x, wb.y));   // (h1_p2, h1_p3)
        float f0, f1, f2, f3;
        up2(ha, f0, f1); up2(hb, f2, f3);
        uint64_t d0 = dup2(f0), d1 = dup2(f1), d2 = dup2(f2), d3 = dup2(f3);
        const ulonglong2* row = W2 + i * 4;           // 16 floats, natural pairs
#pragma unroll
        for (int jj = 0; jj < 4; jj++) {
            ulonglong2 w = row[jj];
            h0[2*jj]   = fma2(d0, w.x, h0[2*jj]);
            h1r[2*jj]  = fma2(d1, w.x, h1r[2*jj]);
            h2r[2*jj]  = fma2(d2, w.x, h2r[2*jj]);
            h3r[2*jj]  = fma2(d3, w.x, h3r[2*jj]);
            h0[2*jj+1] = fma2(d0, w.y, h0[2*jj+1]);
            h1r[2*jj+1]= fma2(d1, w.y, h1r[2*jj+1]);
            h2r[2*jj+1]= fma2(d2, w.y, h2r[2*jj+1]);
            h3r[2*jj+1]= fma2(d3, w.y, h3r[2*jj+1]);
        }
    }
    const ulonglong2* w3v = reinterpret_cast<const ulonglong2*>(p + 328);
    uint64_t b3p = p[336];                            // (b3, 0)
    uint64_t a0 = b3p, a1 = b3p, a2 = b3p, a3 = b3p;
#pragma unroll
    for (int jj = 0; jj < 4; jj++) {
        ulonglong2 w = w3v[jj];
        a0 = fma2(lrelu2(h0[2*jj]),  w.x, a0);  a0 = fma2(lrelu2(h0[2*jj+1]),  w.y, a0);
        a1 = fma2(lrelu2(h1r[2*jj]), w.x, a1);  a1 = fma2(lrelu2(h1r[2*jj+1]), w.y, a1);
        a2 = fma2(lrelu2(h2r[2*jj]), w.x, a2);  a2 = fma2(lrelu2(h2r[2*jj+1]), w.y, a2);
        a3 = fma2(lrelu2(h3r[2*jj]), w.x, a3);  a3 = fma2(lrelu2(h3r[2*jj+1]), w.y, a3);
    }
    float s0, s1, t0, t1, u0, u1, v0, v1;
    up2(a0, s0, s1); up2(a1, t0, t1); up2(a2, u0, u1); up2(a3, v0, v1);
    oa = pk2(s0 + s1, t0 + t1);
    ob = pk2(u0 + u1, v0 + v1);
}

extern __shared__ unsigned long long smw[];

__global__ __launch_bounds__(TPB, 1) void realnvp_kernel(
    const float* __restrict__ x,
    const float* __restrict__ scale_w, const float* __restrict__ scale_b,
    const float* __restrict__ sW1, const float* __restrict__ sb1,
    const float* __restrict__ sW2, const float* __restrict__ sb2,
    const float* __restrict__ sW3, const float* __restrict__ sb3,
    const float* __restrict__ tW1, const float* __restrict__ tb1,
    const float* __restrict__ tW2, const float* __restrict__ tb2,
    const float* __restrict__ tW3, const float* __restrict__ tb3,
    float* __restrict__ out, int nquads)
{
    // Stage weights into shared memory (W1/b1/sw/sb duplicated; rest plain pairs).
    for (int idx = threadIdx.x; idx < SMEM_UNITS; idx += blockDim.x) {
        int l = idx / LAYER_STRIDE;
        int k = idx - l * LAYER_STRIDE;
        unsigned long long unit;
        if (k == 676) { float v = scale_w[l]; unit = pk2(v, v); }
        else if (k == 677) { float v = scale_b[l]; unit = pk2(v, v); }
        else {
            const float *W1 = sW1, *b1 = sb1, *W2 = sW2, *b2 = sb2, *W3 = sW3, *b3 = sb3;
            int kk = k;
            if (k >= 338) { kk = k - 338; W1 = tW1; b1 = tb1; W2 = tW2; b2 = tb2; W3 = tW3; b3 = tb3; }
            if (kk < 64) {
                float v = (kk & 1) ? b1[l * 32 + (kk >> 1)] : W1[l * 32 + (kk >> 1)];
                unit = pk2(v, v);
            } else if (kk < 320) {
                int j = (kk - 64) * 2;
                unit = pk2(W2[l * 512 + j], W2[l * 512 + j + 1]);
            } else if (kk < 328) {
                int j = (kk - 320) * 2;
                unit = pk2(b2[l * 16 + j], b2[l * 16 + j + 1]);
            } else if (kk < 336) {
                int j = (kk - 328) * 2;
                unit = pk2(W3[l * 16 + j], W3[l * 16 + j + 1]);
            } else if (kk == 336) {
                unit = pk2(b3[l], 0.0f);
            } else {
                unit = 0ull;   // pad
            }
        }
        smw[idx] = unit;
    }
    __syncthreads();

    const int stride = gridDim.x * blockDim.x;
    for (int q = blockIdx.x * blockDim.x + threadIdx.x; q < nquads; q += stride) {
        float4 xv0 = *reinterpret_cast<const float4*>(x + 8 * (size_t)q);
        float4 xv1 = *reinterpret_cast<const float4*>(x + 8 * (size_t)q + 4);
        // pack a = points 4q,4q+1 ; pack b = points 4q+2,4q+3
        uint64_t z1a = pk2(xv0.y, xv0.w), z2a = pk2(xv0.x, xv0.z);
        uint64_t z1b = pk2(xv1.y, xv1.w), z2b = pk2(xv1.x, xv1.z);
        uint64_t lda = 0, ldb = 0;

#pragma unroll 1
        for (int l = 0; l < NLAYERS; l++) {
            const unsigned long long* base = smw + l * LAYER_STRIDE;
            uint64_t x1a = z2a, x2a = z1a;
            uint64_t x1b = z2b, x2b = z1b;

            uint64_t sa, sb_;
            mlp2_quad(x1a, x1b, base, sa, sb_);
            float a0, a1, b0, b1;
            up2(sa, a0, a1); up2(sb_, b0, b1);
            uint64_t tha = pk2(fast_tanh(a0), fast_tanh(a1));
            uint64_t thb = pk2(fast_tanh(b0), fast_tanh(b1));
            uint64_t logsa = fma2(tha, base[676], base[677]);
            uint64_t logsb = fma2(thb, base[676], base[677]);

            uint64_t ta, tb;
            mlp2_quad(x1a, x1b, base + 338, ta, tb);

            up2(logsa, a0, a1); up2(logsb, b0, b1);
            uint64_t exa = pk2(__expf(a0), __expf(a1));
            uint64_t exb = pk2(__expf(b0), __expf(b1));
            uint64_t z2na = fma2(exa, x2a, ta);
            uint64_t z2nb = fma2(exb, x2b, tb);

            lda = add2(lda, logsa);
            ldb = add2(ldb, logsb);
            z1a = x1a; z2a = z2na;
            z1b = x1b; z2b = z2nb;
        }

        float z1a0, z1a1, z2a0, z2a1, z1b0, z1b1, z2b0, z2b1;
        float la0, la1, lb0, lb1;
        up2(z1a, z1a0, z1a1); up2(z2a, z2a0, z2a1);
        up2(z1b, z1b0, z1b1); up2(z2b, z2b0, z2b1);
        up2(lda, la0, la1);   up2(ldb, lb0, lb1);

        float4 o0; o0.x = z1a0; o0.y = z2a0; o0.z = z1a1; o0.w = z2a1;
        float4 o1; o1.x = z1b0; o1.y = z2b0; o1.z = z1b1; o1.w = z2b1;
        *reinterpret_cast<float4*>(out + 8 * (size_t)q)     = o0;
        *reinterpret_cast<float4*>(out + 8 * (size_t)q + 4) = o1;
        float4 lo; lo.x = la0; lo.y = la1; lo.z = lb0; lo.w = lb1;
        *reinterpret_cast<float4*>(out + 8 * (size_t)nquads + 4 * (size_t)q) = lo;
    }
}

extern "C" void kernel_launch(void* const* d_in, const int* in_sizes, int n_in,
                              void* d_out, int out_size) {
    const float* x       = (const float*)d_in[0];
    const float* scale_w = (const float*)d_in[1];
    const float* scale_b = (const float*)d_in[2];
    const float* sW1 = (const float*)d_in[3];
    const float* sb1 = (const float*)d_in[4];
    const float* sW2 = (const float*)d_in[5];
    const float* sb2 = (const float*)d_in[6];
    const float* sW3 = (const float*)d_in[7];
    const float* sb3 = (const float*)d_in[8];
    const float* tW1 = (const float*)d_in[9];
    const float* tb1 = (const float*)d_in[10];
    const float* tW2 = (const float*)d_in[11];
    const float* tb2 = (const float*)d_in[12];
    const float* tW3 = (const float*)d_in[13];
    const float* tb3 = (const float*)d_in[14];
    float* out = (float*)d_out;

    int nquads = in_sizes[0] / 8;   // x has N*2 floats; 4 points per thread

    cudaFuncSetAttribute(realnvp_kernel, cudaFuncAttributeMaxDynamicSharedMemorySize, SMEM_BYTES);
    realnvp_kernel<<<148, TPB, SMEM_BYTES>>>(
        x, scale_w, scale_b, sW1, sb1, sW2, sb2, sW3, sb3,
        tW1, tb1, tW2, tb2, tW3, tb3, out, nquads);
}

// round 10
// speedup vs baseline: 7.4670x; 7.4670x over previous
#include <cuda_runtime.h>
#include <cstdint>
#include <math_constants.h>

// RealNVP via EXACT piecewise-linear collapse of the 1->32->16->1 MLPs.
// Each MLP (scalar->scalar, leaky_relu 0.01) is piecewise linear with <=560
// knees (32 first-layer + <=16 per-unit crossings per interval). A prep kernel
// builds, per MLP: sorted knot array B[1024] (B[0]=-inf, +inf padded) and per
// segment (A=left knot, V=f(A) exact, S=slope). Eval = ~7-probe binary search
// + 1 fma instead of ~512 MACs.
// Flow kernel: per-CTA smem-resident state for all 15 layers; per-layer table
// staged into smem. Output: [ (z1,z2) interleaved (N,2) | ld (N,1) ].

#define NLAYERS 15
#define MAXK    1024
#define PREP_T  256
#define MAIN_T  1024
#define QPC     3543          // quads per CTA; grid = ceil(nquads/QPC)

// tables built by prep kernel
__device__ float  g_B[2 * NLAYERS][MAXK];
__device__ float4 g_AVS[2 * NLAYERS][MAXK];
__device__ int    g_p2[2 * NLAYERS];

__device__ __forceinline__ float fast_tanh(float x) {
    float e = __expf(2.0f * x);
    float r = __frcp_rn(e + 1.0f);
    return fmaf(-2.0f, r, 1.0f);
}

// ---------------------------------------------------------------------------
// Prep: one block per MLP (mi = 2*layer + is_t)
// ---------------------------------------------------------------------------
__global__ void prep_kernel(
    const float* __restrict__ sW1, const float* __restrict__ sb1,
    const float* __restrict__ sW2, const float* __restrict__ sb2,
    const float* __restrict__ sW3, const float* __restrict__ sb3,
    const float* __restrict__ tW1, const float* __restrict__ tb1,
    const float* __restrict__ tW2, const float* __restrict__ tb2,
    const float* __restrict__ tW3, const float* __restrict__ tb3)
{
    __shared__ float w1[32], b1[32], W2s[512], b2s[16], w3s[16];
    __shared__ float K[MAXK];
    __shared__ float X[34];
    __shared__ int cnt, m1s;

    int tid = threadIdx.x;
    int mi = blockIdx.x, l = mi >> 1;
    bool ist = mi & 1;
    const float* pW1 = (ist ? tW1 : sW1) + l * 32;
    const float* pb1 = (ist ? tb1 : sb1) + l * 32;
    const float* pW2 = (ist ? tW2 : sW2) + l * 512;
    const float* pb2 = (ist ? tb2 : sb2) + l * 16;
    const float* pW3 = (ist ? tW3 : sW3) + l * 16;
    float b3v = (ist ? tb3 : sb3)[l];

    for (int i = tid; i < 32; i += PREP_T) { w1[i] = pW1[i]; b1[i] = pb1[i]; }
    for (int i = tid; i < 512; i += PREP_T) W2s[i] = pW2[i];
    for (int i = tid; i < 16; i += PREP_T) { b2s[i] = pb2[i]; w3s[i] = pW3[i]; }
    for (int i = tid; i < MAXK; i += PREP_T) K[i] = CUDART_INF_F;
    if (tid == 0) cnt = 0;
    __syncthreads();

    // layer-1 knees
    if (tid < 32 && w1[tid] != 0.0f) {
        int p = atomicAdd(&cnt, 1);
        K[p] = -b1[tid] / w1[tid];
    }
    __syncthreads();

    if (tid == 0) {
        int m1 = cnt; m1s = m1;
        for (int a = 0; a < m1; a++) X[a + 1] = K[a];
        for (int a = 2; a <= m1; a++) {           // insertion sort
            float v = X[a]; int b = a - 1;
            while (b >= 1 && X[b] > v) { X[b + 1] = X[b]; b--; }
            X[b + 1] = v;
        }
        X[0] = -CUDART_INF_F; X[m1 + 1] = CUDART_INF_F;
    }
    __syncthreads();
    int m1 = m1s;

    // layer-2 knees: a2_j is linear within each L1 interval -> <=1 root each
    int ntask = (m1 + 1) * 16;
    for (int t = tid; t < ntask; t += PREP_T) {
        int iv = t >> 4, j = t & 15;
        float lo = X[iv], hi = X[iv + 1];
        float xm;
        if (!isfinite(lo) && !isfinite(hi)) xm = 0.0f;
        else if (!isfinite(lo)) xm = hi - 1.0f;
        else if (!isfinite(hi)) xm = lo + 1.0f;
        else xm = 0.5f * (lo + hi);
        float c = b2s[j], d = 0.0f;
        for (int i = 0; i < 32; i++) {
            float pre = fmaf(w1[i], xm, b1[i]);
            float s1 = (pre >= 0.0f) ? 1.0f : 0.01f;
            float wij = W2s[i * 16 + j];
            d = fmaf(wij * s1, w1[i], d);
            c = fmaf(wij * s1, b1[i], c);
        }
        if (d != 0.0f) {
            float r = -c / d;
            if (isfinite(r) && r > lo && r < hi) {
                int p = atomicAdd(&cnt, 1);
                K[p] = r;
            }
        }
    }
    __syncthreads();
    int m = cnt;

    // bitonic sort K[0..MAXK) ascending (+inf pads sink to the end)
    for (int k = 2; k <= MAXK; k <<= 1) {
        for (int j = k >> 1; j > 0; j >>= 1) {
            __syncthreads();
            for (int t = tid; t < MAXK / 2; t += PREP_T) {
                int i = ((t / j) * (j << 1)) + (t & (j - 1));
                int p = i + j;
                float a = K[i], b = K[p];
                bool up = ((i & k) == 0);
                if (up ? (a > b) : (a < b)) { K[i] = b; K[p] = a; }
            }
        }
    }
    __syncthreads();

    // write B (B[0]=-inf, B[1..m]=knees, rest +inf) and p2
    for (int kk = tid; kk < MAXK; kk += PREP_T) {
        float v = (kk == 0) ? -CUDART_INF_F : (kk <= m ? K[kk - 1] : CUDART_INF_F);
        g_B[mi][kk] = v;
    }
    if (tid == 0) g_p2[mi] = (m > 0) ? (1 << (31 - __clz(m))) : 0;
    __syncthreads();

    // per-segment (A, V, S); segment idx covers [B[idx], B[idx+1])
    for (int idx = tid; idx < MAXK; idx += PREP_T) {
        float4 o = make_float4(0.f, 0.f, 0.f, 0.f);
        if (idx <= m) {
            float Bl = (idx == 0) ? -CUDART_INF_F : K[idx - 1];
            float Br = (idx < m) ? K[idx] : CUDART_INF_F;
            float A  = (idx == 0) ? ((m >= 1) ? K[0] : 0.0f) : K[idx - 1];
            float xm;
            if (idx == 0)      xm = (m >= 1) ? K[0] - 1.0f : 0.0f;
            else if (idx == m) xm = Bl + 1.0f;
            else { xm = 0.5f * (Bl + Br); if (!(xm > Bl && xm < Br)) xm = Bl; }

            // exact value at anchor A
            float acc[16];
#pragma unroll
            for (int j = 0; j < 16; j++) acc[j] = b2s[j];
            for (int i = 0; i < 32; i++) {
                float pre = fmaf(w1[i], A, b1[i]);
                float h = fmaxf(pre, 0.01f * pre);
#pragma unroll
                for (int j = 0; j < 16; j++) acc[j] = fmaf(h, W2s[i * 16 + j], acc[j]);
            }
            float V = b3v;
#pragma unroll
            for (int j = 0; j < 16; j++) {
                float hh = fmaxf(acc[j], 0.01f * acc[j]);
                V = fmaf(hh, w3s[j], V);
            }

            // slope from activation masks at interior point xm
            float a2[16], dd[16];
#pragma unroll
            for (int j = 0; j < 16; j++) { a2[j] = b2s[j]; dd[j] = 0.0f; }
            for (int i = 0; i < 32; i++) {
                float pre = fmaf(w1[i], xm, b1[i]);
                float s1 = (pre >= 0.0f) ? 1.0f : 0.01f;
                float h = s1 * pre;
                float dh = s1 * w1[i];
#pragma unroll
                for (int j = 0; j < 16; j++) {
                    float wij = W2s[i * 16 + j];
                    a2[j] = fmaf(h, wij, a2[j]);
                    dd[j] = fmaf(dh, wij, dd[j]);
                }
            }
            float S = 0.0f;
#pragma unroll
            for (int j = 0; j < 16; j++) {
                float s2 = (a2[j] >= 0.0f) ? 1.0f : 0.01f;
                S = fmaf(w3s[j] * s2, dd[j], S);
            }
            o = make_float4(A, V, S, 0.0f);
        }
        g_AVS[mi][idx] = o;
    }
}

// ---------------------------------------------------------------------------
// Flow kernel
// ---------------------------------------------------------------------------
__device__ __forceinline__ float pwl_eval(const float* __restrict__ B,
                                          const float4* __restrict__ AVS,
                                          int p2, float x) {
    int idx = 0;
    for (int step = p2; step > 0; step >>= 1)
        if (B[idx + step] <= x) idx += step;
    float4 a = AVS[idx];
    return fmaf(a.z, x - a.x, a.y);
}

extern __shared__ float4 smb[];

__global__ __launch_bounds__(MAIN_T, 1) void flow_kernel(
    const float* __restrict__ x,
    const float* __restrict__ scale_w, const float* __restrict__ scale_b,
    float* __restrict__ out, int nquads)
{
    float4* As  = smb;
    float4* At  = As + MAXK;
    float4* SZ1 = At + MAXK;
    float4* SZ2 = SZ1 + QPC;
    float4* SLD = SZ2 + QPC;
    float*  Bs  = (float*)(SLD + QPC);
    float*  Bt  = Bs + MAXK;

    int tid = threadIdx.x;
    int q0 = blockIdx.x * QPC;
    int nq = nquads - q0;
    if (nq > QPC) nq = QPC;

    const float4* x4 = (const float4*)x;
    for (int lq = tid; lq < nq; lq += MAIN_T) {
        int Q = q0 + lq;
        float4 a = x4[2 * Q], b = x4[2 * Q + 1];
        SZ1[lq] = make_float4(a.y, a.w, b.y, b.w);   // x[:,1]
        SZ2[lq] = make_float4(a.x, a.z, b.x, b.z);   // x[:,0]
        SLD[lq] = make_float4(0.f, 0.f, 0.f, 0.f);
    }

    for (int l = 0; l < NLAYERS; l++) {
        __syncthreads();
        {
            const float*  gBs = g_B[2 * l];
            const float*  gBt = g_B[2 * l + 1];
            const float4* gAs = g_AVS[2 * l];
            const float4* gAt = g_AVS[2 * l + 1];
            for (int k = tid; k < MAXK; k += MAIN_T) {
                Bs[k] = gBs[k]; Bt[k] = gBt[k];
                As[k] = gAs[k]; At[k] = gAt[k];
            }
        }
        int p2s = g_p2[2 * l], p2t = g_p2[2 * l + 1];
        float sw = scale_w[l], sb = scale_b[l];
        __syncthreads();

        for (int lq = tid; lq < nq; lq += MAIN_T) {
            float4 z1 = SZ1[lq], z2 = SZ2[lq], ld = SLD[lq];
            float x1v[4] = {z2.x, z2.y, z2.z, z2.w};
            float x2v[4] = {z1.x, z1.y, z1.z, z1.w};
            float zn[4], lg[4];
#pragma unroll
            for (int e = 0; e < 4; e++) {
                float x1 = x1v[e];
                float sv = pwl_eval(Bs, As, p2s, x1);
                float tv = pwl_eval(Bt, At, p2t, x1);
                float logs = fmaf(fast_tanh(sv), sw, sb);
                zn[e] = fmaf(__expf(logs), x2v[e], tv);
                lg[e] = logs;
            }
            SZ1[lq] = z2;                                     // new z1 = x1
            SZ2[lq] = make_float4(zn[0], zn[1], zn[2], zn[3]);
            SLD[lq] = make_float4(ld.x + lg[0], ld.y + lg[1],
                                  ld.z + lg[2], ld.w + lg[3]);
        }
    }
    __syncthreads();

    float4* o4  = (float4*)out;
    float4* ld4 = (float4*)(out + 8 * (size_t)nquads);
    for (int lq = tid; lq < nq; lq += MAIN_T) {
        int Q = q0 + lq;
        float4 z1 = SZ1[lq], z2 = SZ2[lq];
        o4[2 * Q]     = make_float4(z1.x, z2.x, z1.y, z2.y);
        o4[2 * Q + 1] = make_float4(z1.z, z2.z, z1.w, z2.w);
        ld4[Q] = SLD[lq];
    }
}

extern "C" void kernel_launch(void* const* d_in, const int* in_sizes, int n_in,
                              void* d_out, int out_size) {
    const float* x       = (const float*)d_in[0];
    const float* scale_w = (const float*)d_in[1];
    const float* scale_b = (const float*)d_in[2];
    const float* sW1 = (const float*)d_in[3];
    const float* sb1 = (const float*)d_in[4];
    const float* sW2 = (const float*)d_in[5];
    const float* sb2 = (const float*)d_in[6];
    const float* sW3 = (const float*)d_in[7];
    const float* sb3 = (const float*)d_in[8];
    const float* tW1 = (const float*)d_in[9];
    const float* tb1 = (const float*)d_in[10];
    const float* tW2 = (const float*)d_in[11];
    const float* tb2 = (const float*)d_in[12];
    const float* tW3 = (const float*)d_in[13];
    const float* tb3 = (const float*)d_in[14];
    float* out = (float*)d_out;

    int nquads = in_sizes[0] / 8;
    int grid = (nquads + QPC - 1) / QPC;   // 296 for N=4194304

    const int smem_main = 2 * MAXK * 16 + 3 * QPC * 16 + 2 * MAXK * 4; // 211,024 B
    cudaFuncSetAttribute(flow_kernel, cudaFuncAttributeMaxDynamicSharedMemorySize, smem_main);

    prep_kernel<<<2 * NLAYERS, PREP_T>>>(sW1, sb1, sW2, sb2, sW3, sb3,
                                         tW1, tb1, tW2, tb2, tW3, tb3);
    flow_kernel<<<grid, MAIN_T, smem_main>>>(x, scale_w, scale_b, out, nquads);
}

// round 11
// speedup vs baseline: 10.3325x; 1.3837x over previous
#include <cuda_runtime.h>
#include <cstdint>
#include <math_constants.h>

// RealNVP via exact piecewise-linear collapse (R10: 428us) with two upgrades:
//  (1) s & t MLP knot sets MERGED per layer -> one locate serves both evals
//      (payload per segment: A, Vs, Ss, Vt, St).
//  (2) uniform-grid jump start (2048 cells, uint16 start index) + short
//      forward walk replaces the ~10-probe binary search.
// Output: [ (z1,z2) interleaved (N,2) | ld (N,1) ].

#define NLAYERS 15
#define MAXK    1280          // merged knees bound: 2*560=1120
#define KSORT   2048          // bitonic sort width
#define GCELLS  2048
#define PREP_T  256
#define MAIN_T  1024
#define QPC     3543          // quads per CTA; grid = 296 for N=4194304

__device__ float  g_B [NLAYERS][MAXK];      // knots; B[0]=-inf, +inf padded
__device__ float4 g_AV[NLAYERS][MAXK];      // (A, Vs, Ss, Vt)
__device__ float  g_St[NLAYERS][MAXK];      // St
__device__ unsigned short g_grid[NLAYERS][GCELLS];
__device__ float  g_x0[NLAYERS], g_invh[NLAYERS];

__device__ __forceinline__ float fast_tanh(float x) {
    float e = __expf(2.0f * x);
    float r = __frcp_rn(e + 1.0f);
    return fmaf(-2.0f, r, 1.0f);
}

// ---------------------------------------------------------------------------
// Prep: one block per LAYER; builds the merged table.
// ---------------------------------------------------------------------------
__global__ void prep_kernel(
    const float* __restrict__ sW1, const float* __restrict__ sb1,
    const float* __restrict__ sW2, const float* __restrict__ sb2,
    const float* __restrict__ sW3, const float* __restrict__ sb3,
    const float* __restrict__ tW1, const float* __restrict__ tb1,
    const float* __restrict__ tW2, const float* __restrict__ tb2,
    const float* __restrict__ tW3, const float* __restrict__ tb3)
{
    __shared__ float w1[2][32], b1[2][32], W2s[2][512], b2s[2][16], w3s[2][16], b3s[2];
    __shared__ float K[KSORT];
    __shared__ float X[34];
    __shared__ int cnt, m1s;

    int tid = threadIdx.x;
    int l = blockIdx.x;

    for (int i = tid; i < 32; i += PREP_T) {
        w1[0][i] = sW1[l*32+i]; b1[0][i] = sb1[l*32+i];
        w1[1][i] = tW1[l*32+i]; b1[1][i] = tb1[l*32+i];
    }
    for (int i = tid; i < 512; i += PREP_T) {
        W2s[0][i] = sW2[l*512+i]; W2s[1][i] = tW2[l*512+i];
    }
    for (int i = tid; i < 16; i += PREP_T) {
        b2s[0][i] = sb2[l*16+i]; w3s[0][i] = sW3[l*16+i];
        b2s[1][i] = tb2[l*16+i]; w3s[1][i] = tW3[l*16+i];
    }
    if (tid == 0) { b3s[0] = sb3[l]; b3s[1] = tb3[l]; cnt = 0; }
    for (int i = tid; i < KSORT; i += PREP_T) K[i] = CUDART_INF_F;
    __syncthreads();

    // knees for each MLP
    for (int p = 0; p < 2; p++) {
        if (tid == 0) {
            int m1 = 0;
            for (int i = 0; i < 32; i++)
                if (w1[p][i] != 0.0f) X[++m1] = -b1[p][i] / w1[p][i];
            for (int a = 2; a <= m1; a++) {          // insertion sort X[1..m1]
                float v = X[a]; int b = a - 1;
                while (b >= 1 && X[b] > v) { X[b + 1] = X[b]; b--; }
                X[b + 1] = v;
            }
            X[0] = -CUDART_INF_F; X[m1 + 1] = CUDART_INF_F;
            m1s = m1;
            int c0 = cnt;
            for (int a = 1; a <= m1; a++) K[c0 + a - 1] = X[a];  // L1 knees
            cnt = c0 + m1;
        }
        __syncthreads();
        int m1 = m1s;
        int ntask = (m1 + 1) * 16;
        for (int t = tid; t < ntask; t += PREP_T) {
            int iv = t >> 4, j = t & 15;
            float lo = X[iv], hi = X[iv + 1];
            float xm;
            if (!isfinite(lo) && !isfinite(hi)) xm = 0.0f;
            else if (!isfinite(lo)) xm = hi - 1.0f;
            else if (!isfinite(hi)) xm = lo + 1.0f;
            else xm = 0.5f * (lo + hi);
            float c = b2s[p][j], d = 0.0f;
            for (int i = 0; i < 32; i++) {
                float pre = fmaf(w1[p][i], xm, b1[p][i]);
                float s1 = (pre >= 0.0f) ? 1.0f : 0.01f;
                float wij = W2s[p][i * 16 + j];
                d = fmaf(wij * s1, w1[p][i], d);
                c = fmaf(wij * s1, b1[p][i], c);
            }
            if (d != 0.0f) {
                float r = -c / d;
                if (isfinite(r) && r > lo && r < hi) {
                    int pos = atomicAdd(&cnt, 1);
                    K[pos] = r;
                }
            }
        }
        __syncthreads();
    }
    int m = cnt;

    // bitonic sort K[0..KSORT)
    for (int k = 2; k <= KSORT; k <<= 1) {
        for (int j = k >> 1; j > 0; j >>= 1) {
            __syncthreads();
            for (int t = tid; t < KSORT / 2; t += PREP_T) {
                int i = ((t / j) * (j << 1)) + (t & (j - 1));
                int q = i + j;
                float a = K[i], b = K[q];
                bool up = ((i & k) == 0);
                if (up ? (a > b) : (a < b)) { K[i] = b; K[q] = a; }
            }
        }
    }
    __syncthreads();

    // write B: B[0]=-inf, B[1..m]=K[0..m-1], rest +inf
    for (int kk = tid; kk < MAXK; kk += PREP_T) {
        float v = (kk == 0) ? -CUDART_INF_F : (kk <= m ? K[kk - 1] : CUDART_INF_F);
        g_B[l][kk] = v;
    }
    __syncthreads();

    // per-segment payload (A, Vs, Ss, Vt, St); segment idx covers [B[idx],B[idx+1])
    for (int idx = tid; idx <= m; idx += PREP_T) {
        float Bl = (idx == 0) ? -CUDART_INF_F : K[idx - 1];
        float Br = (idx < m) ? K[idx] : CUDART_INF_F;
        float A  = isfinite(Bl) ? Bl : ((m >= 1) ? K[0] : 0.0f);
        float xm;
        if (!isfinite(Bl) && !isfinite(Br)) xm = 0.0f;
        else if (!isfinite(Bl)) xm = Br - 1.0f;
        else if (!isfinite(Br)) xm = Bl + 1.0f;
        else { xm = 0.5f * (Bl + Br); if (!(xm > Bl && xm < Br)) xm = Bl; }

        float V[2], S[2];
        for (int p = 0; p < 2; p++) {
            // exact value at anchor A
            float acc[16];
#pragma unroll
            for (int j = 0; j < 16; j++) acc[j] = b2s[p][j];
            for (int i = 0; i < 32; i++) {
                float pre = fmaf(w1[p][i], A, b1[p][i]);
                float h = fmaxf(pre, 0.01f * pre);
#pragma unroll
                for (int j = 0; j < 16; j++) acc[j] = fmaf(h, W2s[p][i * 16 + j], acc[j]);
            }
            float Vv = b3s[p];
#pragma unroll
            for (int j = 0; j < 16; j++) {
                float hh = fmaxf(acc[j], 0.01f * acc[j]);
                Vv = fmaf(hh, w3s[p][j], Vv);
            }
            // slope from activation masks at interior xm
            float a2[16], dd[16];
#pragma unroll
            for (int j = 0; j < 16; j++) { a2[j] = b2s[p][j]; dd[j] = 0.0f; }
            for (int i = 0; i < 32; i++) {
                float pre = fmaf(w1[p][i], xm, b1[p][i]);
                float s1 = (pre >= 0.0f) ? 1.0f : 0.01f;
                float h = s1 * pre;
                float dh = s1 * w1[p][i];
#pragma unroll
                for (int j = 0; j < 16; j++) {
                    float wij = W2s[p][i * 16 + j];
                    a2[j] = fmaf(h, wij, a2[j]);
                    dd[j] = fmaf(dh, wij, dd[j]);
                }
            }
            float Sv = 0.0f;
#pragma unroll
            for (int j = 0; j < 16; j++) {
                float s2 = (a2[j] >= 0.0f) ? 1.0f : 0.01f;
                Sv = fmaf(w3s[p][j] * s2, dd[j], Sv);
            }
            V[p] = Vv; S[p] = Sv;
        }
        g_AV[l][idx] = make_float4(A, V[0], S[0], V[1]);
        g_St[l][idx] = S[1];
    }
    // zero tail (never read, but keep deterministic)
    for (int idx = m + 1 + tid; idx < MAXK; idx += PREP_T) {
        g_AV[l][idx] = make_float4(0.f, 0.f, 0.f, 0.f);
        g_St[l][idx] = 0.f;
    }
    __syncthreads();

    // uniform grid
    float x0 = (m >= 1) ? K[0] : 0.0f;
    float xr = (m >= 1) ? K[m - 1] : 0.0f;
    float invh = (m >= 2 && xr > x0) ? (float)GCELLS / (xr - x0) : 0.0f;
    float h = (invh > 0.0f) ? (xr - x0) / (float)GCELLS : 0.0f;
    if (tid == 0) { g_x0[l] = x0; g_invh[l] = invh; }
    for (int g = tid; g < GCELLS; g += PREP_T) {
        int idx = 0;
        if (g > 0 && m >= 1) {
            float xc = x0 + (float)g * h;
            // largest idx with B[idx] <= xc  (B[i]=K[i-1] for 1<=i<=m)
            int lo = 0, hi = m;               // idx in [0, m]
            while (lo < hi) {
                int mid = (lo + hi + 1) >> 1;
                float bv = K[mid - 1];
                if (bv <= xc) lo = mid; else hi = mid - 1;
            }
            idx = lo;
        }
        g_grid[l][g] = (unsigned short)idx;
    }
}

// ---------------------------------------------------------------------------
// Flow kernel
// ---------------------------------------------------------------------------
extern __shared__ float4 smb[];

__global__ __launch_bounds__(MAIN_T, 1) void flow_kernel(
    const float* __restrict__ x,
    const float* __restrict__ scale_w, const float* __restrict__ scale_b,
    float* __restrict__ out, int nquads)
{
    float4* AVs = smb;                     // MAXK float4
    float4* SZ1 = AVs + MAXK;              // QPC
    float4* SZ2 = SZ1 + QPC;
    float4* SLD = SZ2 + QPC;
    float*  Bs  = (float*)(SLD + QPC);     // MAXK
    float*  Sts = Bs + MAXK;               // MAXK
    unsigned short* Gs = (unsigned short*)(Sts + MAXK);  // GCELLS

    int tid = threadIdx.x;
    int q0 = blockIdx.x * QPC;
    int nq = nquads - q0;
    if (nq > QPC) nq = QPC;

    const float4* x4 = (const float4*)x;
    for (int lq = tid; lq < nq; lq += MAIN_T) {
        int Q = q0 + lq;
        float4 a = x4[2 * Q], b = x4[2 * Q + 1];
        SZ1[lq] = make_float4(a.y, a.w, b.y, b.w);   // x[:,1]
        SZ2[lq] = make_float4(a.x, a.z, b.x, b.z);   // x[:,0]
        SLD[lq] = make_float4(0.f, 0.f, 0.f, 0.f);
    }

    for (int l = 0; l < NLAYERS; l++) {
        __syncthreads();
        {
            const float*  gB = g_B[l];
            const float4* gA = g_AV[l];
            const float*  gS = g_St[l];
            const unsigned short* gG = g_grid[l];
            for (int k = tid; k < MAXK; k += MAIN_T) {
                Bs[k] = gB[k]; AVs[k] = gA[k]; Sts[k] = gS[k];
            }
            for (int g = tid; g < GCELLS; g += MAIN_T) Gs[g] = gG[g];
        }
        float x0 = g_x0[l], invh = g_invh[l];
        float sw = scale_w[l], sb = scale_b[l];
        __syncthreads();

        for (int lq = tid; lq < nq; lq += MAIN_T) {
            float4 z1 = SZ1[lq], z2 = SZ2[lq], ld = SLD[lq];
            float x1v[4] = {z2.x, z2.y, z2.z, z2.w};
            float x2v[4] = {z1.x, z1.y, z1.z, z1.w};
            float zn[4], lg[4];
#pragma unroll
            for (int e = 0; e < 4; e++) {
                float xv = x1v[e];
                int c = (int)((xv - x0) * invh);
                c = min(max(c, 0), GCELLS - 1);
                int idx = Gs[c];
                while (Bs[idx + 1] <= xv) idx++;
                float4 av = AVs[idx];
                float st = Sts[idx];
                float dx = xv - av.x;
                float sv = fmaf(av.z, dx, av.y);
                float tv = fmaf(st,   dx, av.w);
                float logs = fmaf(fast_tanh(sv), sw, sb);
                zn[e] = fmaf(__expf(logs), x2v[e], tv);
                lg[e] = logs;
            }
            SZ1[lq] = z2;                                     // new z1 = x1
            SZ2[lq] = make_float4(zn[0], zn[1], zn[2], zn[3]);
            SLD[lq] = make_float4(ld.x + lg[0], ld.y + lg[1],
                                  ld.z + lg[2], ld.w + lg[3]);
        }
    }
    __syncthreads();

    float4* o4  = (float4*)out;
    float4* ld4 = (float4*)(out + 8 * (size_t)nquads);
    for (int lq = tid; lq < nq; lq += MAIN_T) {
        int Q = q0 + lq;
        float4 z1 = SZ1[lq], z2 = SZ2[lq];
        o4[2 * Q]     = make_float4(z1.x, z2.x, z1.y, z2.y);
        o4[2 * Q + 1] = make_float4(z1.z, z2.z, z1.w, z2.w);
        ld4[Q] = SLD[lq];
    }
}

extern "C" void kernel_launch(void* const* d_in, const int* in_sizes, int n_in,
                              void* d_out, int out_size) {
    const float* x       = (const float*)d_in[0];
    const float* scale_w = (const float*)d_in[1];
    const float* scale_b = (const float*)d_in[2];
    const float* sW1 = (const float*)d_in[3];
    const float* sb1 = (const float*)d_in[4];
    const float* sW2 = (const float*)d_in[5];
    const float* sb2 = (const float*)d_in[6];
    const float* sW3 = (const float*)d_in[7];
    const float* sb3 = (const float*)d_in[8];
    const float* tW1 = (const float*)d_in[9];
    const float* tb1 = (const float*)d_in[10];
    const float* tW2 = (const float*)d_in[11];
    const float* tb2 = (const float*)d_in[12];
    const float* tW3 = (const float*)d_in[13];
    const float* tb3 = (const float*)d_in[14];
    float* out = (float*)d_out;

    int nquads = in_sizes[0] / 8;
    int grid = (nquads + QPC - 1) / QPC;   // 296 for N=4194304

    // smem: AV(float4) + 3*QPC(float4) + B + St (float) + grid (u16)
    const int smem_main = MAXK * 16 + 3 * QPC * 16 + 2 * MAXK * 4 + GCELLS * 2;
    cudaFuncSetAttribute(flow_kernel, cudaFuncAttributeMaxDynamicSharedMemorySize, smem_main);

    prep_kernel<<<NLAYERS, PREP_T>>>(sW1, sb1, sW2, sb2, sW3, sb3,
                                     tW1, tb1, tW2, tb2, tW3, tb3);
    flow_kernel<<<grid, MAIN_T, smem_main>>>(x, scale_w, scale_b, out, nquads);
}